// round 5
// baseline (speedup 1.0000x reference)
#include <cuda_runtime.h>

#define Ec   128
#define Wc   128
#define Vc   7
#define Sc   2048
#define Bc   16
#define P    2                   // o-dimension split
#define OPP  (Ec / P)            // o's per g-block (64)
#define NG   (Ec * P)            // number of g-blocks (256)
#define NT   128

// Scratch (flags reset at end of every run -> deterministic across replays)
__device__ int   d_tok[Bc * Wc];     // window tokens, 7 = pad sentinel
__device__ float d_part[Bc * NG];    // per-(b, g-block) partial sums
__device__ int   d_tokready;         // counter blocks completed
__device__ int   d_arrive;           // g blocks completed

__global__ void __launch_bounds__(NT, 1)
fused_kernel(const void* __restrict__ xraw,
             const float* __restrict__ emb,
             const float* __restrict__ fc_w,
             const float* __restrict__ fc_b,
             const float* __restrict__ out_w,
             const float* __restrict__ out_b,
             float* __restrict__ out) {
    const int blk = blockIdx.x;
    const int k   = threadIdx.x;

    if (blk < Bc) {
        // ================= counter block: batch b = blk =================
        const int b = blk;
        __shared__ int   sred[NT / 32];
        __shared__ float sc0;

        // dtype detection: tokens in [0,7) => int64 iff all odd 32-bit words
        // of the first 8KB are zero (8KB in-bounds for both layouts).
        const int* xw = (const int*)xraw;
        int any = 0;
        for (int i = k; i < 2048; i += NT)
            if ((i & 1) && xw[i] != 0) any = 1;
        any = __any_sync(0xffffffffu, any) ? 1 : 0;
        if ((k & 31) == 0) sred[k >> 5] = any;
        __syncthreads();
        const int is32 = sred[0] | sred[1] | sred[2] | sred[3];
        __syncthreads();

        // count non-pad tokens in row b
        int cnt = 0;
        if (is32) {
            const int* xr = (const int*)xraw + b * Sc;
            for (int s = k; s < Sc; s += NT) cnt += (xr[s] != 0);
        } else {
            const long long* xr = (const long long*)xraw + b * Sc;
            for (int s = k; s < Sc; s += NT) cnt += (xr[s] != 0);
        }
#pragma unroll
        for (int off = 16; off; off >>= 1)
            cnt += __shfl_down_sync(0xffffffffu, cnt, off);
        if ((k & 31) == 0) sred[k >> 5] = cnt;
        __syncthreads();
        const int t = (sred[0] + sred[1] + sred[2] + sred[3]) - 1;

        // publish window tokens (7 = pad sentinel -> zeroed emb row)
        const int p = t - (Wc - 1) + k;
        int tok = Vc;
        if (p >= 0)
            tok = is32 ? ((const int*)xraw)[b * Sc + p]
                       : (int)((const long long*)xraw)[b * Sc + p];
        d_tok[b * Wc + k] = tok;
        __threadfence();
        __syncthreads();
        if (k == 0) atomicAdd(&d_tokready, 1);

        if (b != 0) return;

        // ---- block 0 doubles as the final reducer ----
        float c = out_w[k] * fc_b[k];
#pragma unroll
        for (int off = 16; off; off >>= 1)
            c += __shfl_down_sync(0xffffffffu, c, off);
        __shared__ float scc[NT / 32];
        if ((k & 31) == 0) scc[k >> 5] = c;
        __syncthreads();
        if (k == 0) sc0 = scc[0] + scc[1] + scc[2] + scc[3] + out_b[0];

        if (k == 0)
            while (*(volatile int*)&d_arrive < NG) __nanosleep(32);
        __syncthreads();
        __threadfence();

        // thread k: batch bb = k/8, slice i = k%8 (32 contiguous entries each)
        const int bb = k >> 3, i = k & 7;
        float s = 0.0f;
#pragma unroll
        for (int j = 0; j < NG / 8; j++)
            s += d_part[bb * NG + i * (NG / 8) + j];
#pragma unroll
        for (int off = 4; off; off >>= 1)
            s += __shfl_down_sync(0xffffffffu, s, off, 8);
        if (i == 0) out[bb] = s + sc0;

        __syncthreads();
        if (k == 0) {               // reset flags for next graph replay
            d_arrive = 0;
            d_tokready = 0;
            __threadfence();
        }
        return;
    }

    // ================= g block: gb = blk - Bc =================
    const int gb = blk - Bc;
    const int e  = gb >> 1;              // 0..127
    const int ph = gb & 1;               // o-half
    __shared__ float s_w[Ec];
    __shared__ float s_emb[8 * 129];     // row 7 zeroed (pad sentinel)
    __shared__ float sp[Bc][NT / 32];

    s_w[k] = out_w[k];
    for (int i = k; i < 8 * Ec; i += NT)
        s_emb[(i >> 7) * 129 + (i & 127)] = (i < Vc * Ec) ? emb[i] : 0.0f;
    __syncthreads();

    // partial g[e*128+k] over o in [ph*64, ph*64+64). Explicitly staged loads
    // force 32 outstanding LDGs (MLP=32) regardless of ptxas scheduling mood.
    const float* fw = fc_w + e * Wc + k;
    float acc = 0.0f;
#pragma unroll
    for (int o0 = ph * OPP; o0 < ph * OPP + OPP; o0 += 32) {
        float vals[32];
#pragma unroll
        for (int u = 0; u < 32; u++)
            vals[u] = fw[(size_t)(o0 + u) * (Ec * Wc)];
#pragma unroll
        for (int u = 0; u < 32; u++)
            acc = fmaf(s_w[o0 + u], vals[u], acc);
    }

    // wait for tokens (published long before the stream finishes)
    if (k == 0)
        while (*(volatile int*)&d_tokready < Bc) __nanosleep(32);
    __syncthreads();
    __threadfence();

    int toks[Bc];
#pragma unroll
    for (int b = 0; b < Bc; b++)
        toks[b] = d_tok[b * Wc + k];

    const int wid = k >> 5, lid = k & 31;
#pragma unroll
    for (int b = 0; b < Bc; b++) {
        float v = s_emb[toks[b] * 129 + e] * acc;   // bank=(tok+e)%32: conflict-free
#pragma unroll
        for (int off = 16; off; off >>= 1)
            v += __shfl_down_sync(0xffffffffu, v, off);
        if (lid == 0) sp[b][wid] = v;
    }
    __syncthreads();
    if (k < Bc)
        d_part[k * NG + gb] = sp[k][0] + sp[k][1] + sp[k][2] + sp[k][3];
    __threadfence();
    __syncthreads();
    if (k == 0) atomicAdd(&d_arrive, 1);
}

extern "C" void kernel_launch(void* const* d_in, const int* in_sizes, int n_in,
                              void* d_out, int out_size) {
    const void*  x     = d_in[0];                      // [16,2048] int64 or int32
    const float* emb   = (const float*)d_in[1];        // [7,128]
    const float* fc_w  = (const float*)d_in[2];        // [128,16384]
    const float* fc_b  = (const float*)d_in[3];        // [128]
    const float* out_w = (const float*)d_in[4];        // [1,128]
    const float* out_b = (const float*)d_in[5];        // [1]
    float* out = (float*)d_out;                        // [16]

    fused_kernel<<<Bc + NG, NT>>>(x, emb, fc_w, fc_b, out_w, out_b, out);
}

// round 6
// speedup vs baseline: 1.7619x; 1.7619x over previous
#include <cuda_runtime.h>

#define Ec   128
#define Wc   128
#define Vc   7
#define Sc   2048
#define Bc   16
#define GBLK 128                 // g blocks (one per e); + Bc final blocks = 144
#define NT   256                 // threads per block (two o-/e-halves)

// Scratch (counters return to 0 at end of every run -> deterministic replays)
__device__ float d_g[Ec * Wc];
__device__ int   d_arrive;       // g blocks completed
__device__ int   d_done;         // final blocks completed

__global__ void __launch_bounds__(NT, 1)
fused_kernel(const void* __restrict__ xraw,
             const float* __restrict__ emb,
             const float* __restrict__ fc_w,
             const float* __restrict__ fc_b,
             const float* __restrict__ out_w,
             const float* __restrict__ out_b,
             float* __restrict__ out) {
    const int blk = blockIdx.x;
    const int tid = threadIdx.x;
    const int k   = tid & 127;           // column / window tap
    const int h   = tid >> 7;            // half (0/1)

    if (blk < GBLK) {
        // ========== g block: e = blk, half h covers o in [h*64, h*64+64) ==========
        const int e = blk;
        __shared__ float s_w[Ec];
        __shared__ float s_acc[NT];
        if (tid < Ec) s_w[tid] = out_w[tid];
        __syncthreads();

        const float* fw = fc_w + e * Wc + k;
        float acc = 0.0f;
#pragma unroll
        for (int b = 0; b < 2; b++) {            // 2 batches x 32 staged loads
            float vals[32];
#pragma unroll
            for (int u = 0; u < 32; u++)
                vals[u] = fw[(size_t)(h * 64 + b * 32 + u) * (Ec * Wc)];
#pragma unroll
            for (int u = 0; u < 32; u++)
                acc = fmaf(s_w[h * 64 + b * 32 + u], vals[u], acc);
        }
        s_acc[tid] = acc;
        __syncthreads();
        if (tid < Wc)
            d_g[e * Wc + tid] = s_acc[tid] + s_acc[tid + 128];
        __threadfence();
        __syncthreads();
        if (tid == 0) atomicAdd(&d_arrive, 1);
        return;
    }

    // ========== final block: batch b = blk - GBLK (fully self-contained) ==========
    const int b = blk - GBLK;
    __shared__ int   sred[NT / 32];
    __shared__ float sfl[NT / 32];
    __shared__ int   s_tok[Wc];
    __shared__ float s_emb[8 * 129];     // row 7 zeroed (pad sentinel)
    const int wid = tid >> 5, lid = tid & 31;

    // stage emb
    for (int i = tid; i < 8 * Ec; i += NT)
        s_emb[(i >> 7) * 129 + (i & 127)] = (i < Vc * Ec) ? emb[i] : 0.0f;

    // dtype detection: tokens in [0,7) => int64 iff all odd 32-bit words of the
    // first 8KB are zero (8KB is in-bounds for both layouts).
    const int* xw = (const int*)xraw;
    int any = 0;
    for (int i = tid; i < 2048; i += NT)
        if ((i & 1) && xw[i] != 0) any = 1;
    any = __any_sync(0xffffffffu, any) ? 1 : 0;
    if (lid == 0) sred[wid] = any;
    __syncthreads();
    int is32 = 0;
#pragma unroll
    for (int i = 0; i < NT / 32; i++) is32 |= sred[i];
    __syncthreads();

    // count non-pad tokens in row b
    int cnt = 0;
    if (is32) {
        const int* xr = (const int*)xraw + b * Sc;
#pragma unroll
        for (int s = tid; s < Sc; s += NT) cnt += (xr[s] != 0);
    } else {
        const long long* xr = (const long long*)xraw + b * Sc;
#pragma unroll
        for (int s = tid; s < Sc; s += NT) cnt += (xr[s] != 0);
    }
#pragma unroll
    for (int off = 16; off; off >>= 1)
        cnt += __shfl_down_sync(0xffffffffu, cnt, off);
    if (lid == 0) sred[wid] = cnt;
    __syncthreads();
    int t = -1;
#pragma unroll
    for (int i = 0; i < NT / 32; i++) t += sred[i];

    // fetch window tokens into shared (tap k; sentinel 7 -> zero emb row)
    if (tid < Wc) {
        const int p = t - (Wc - 1) + tid;
        int tok = Vc;
        if (p >= 0)
            tok = is32 ? ((const int*)xraw)[b * Sc + p]
                       : (int)((const long long*)xraw)[b * Sc + p];
        s_tok[tid] = tok;
    }
    __syncthreads();

    // wait for all g rows
    if (tid == 0)
        while (*(volatile int*)&d_arrive < GBLK) __nanosleep(32);
    __syncthreads();
    __threadfence();   // acquire d_g

    // thread (k, h): tap k, e in [h*64, h*64+64), staged L2 loads (MLP=16)
    const int tok = s_tok[k];
    float acc = (h == 0) ? out_w[k] * fc_b[k] : 0.0f;   // fold bias dot
    const float* er = &s_emb[tok * 129 + h * 64];
    const float* gp = &d_g[(h * 64) * Wc + k];
#pragma unroll
    for (int bb = 0; bb < 4; bb++) {
        float vals[16];
#pragma unroll
        for (int u = 0; u < 16; u++)
            vals[u] = gp[(bb * 16 + u) * Wc];
#pragma unroll
        for (int u = 0; u < 16; u++)
            acc = fmaf(er[bb * 16 + u], vals[u], acc);
    }

    // block reduction over all 256 threads
#pragma unroll
    for (int off = 16; off; off >>= 1)
        acc += __shfl_down_sync(0xffffffffu, acc, off);
    if (lid == 0) sfl[wid] = acc;
    __syncthreads();
    if (tid == 0) {
        float s = 0.0f;
#pragma unroll
        for (int i = 0; i < NT / 32; i++) s += sfl[i];
        out[b] = s + out_b[0];
    }

    // reset counters for next graph replay
    __threadfence();
    __syncthreads();
    if (tid == 0) {
        int d = atomicAdd(&d_done, 1);
        if (d == Bc - 1) {      // last final block; every spin already released
            d_arrive = 0;
            d_done   = 0;
            __threadfence();
        }
    }
}

extern "C" void kernel_launch(void* const* d_in, const int* in_sizes, int n_in,
                              void* d_out, int out_size) {
    const void*  x     = d_in[0];                      // [16,2048] int64 or int32
    const float* emb   = (const float*)d_in[1];        // [7,128]
    const float* fc_w  = (const float*)d_in[2];        // [128,16384]
    const float* fc_b  = (const float*)d_in[3];        // [128]
    const float* out_w = (const float*)d_in[4];        // [1,128]
    const float* out_b = (const float*)d_in[5];        // [1]
    float* out = (float*)d_out;                        // [16]

    fused_kernel<<<GBLK + Bc, NT>>>(x, emb, fc_w, fc_b, out_w, out_b, out);
}

// round 8
// speedup vs baseline: 1.8328x; 1.0402x over previous
#include <cuda_runtime.h>

#define Ec   128
#define Wc   128
#define Vc   7
#define Sc   2048
#define Bc   16
#define GBLK 128                 // g blocks (one per e); + Bc final blocks = 144
#define NT   256

// Scratch (counters return to 0 at end of every run -> deterministic replays)
__device__ float d_g[Ec * Wc];
__device__ int   d_arrive;       // g blocks completed
__device__ int   d_done;         // final blocks completed

__global__ void __launch_bounds__(NT, 1)
fused_kernel(const void* __restrict__ xraw,
             const float* __restrict__ emb,
             const float* __restrict__ fc_w,
             const float* __restrict__ fc_b,
             const float* __restrict__ out_w,
             const float* __restrict__ out_b,
             float* __restrict__ out) {
    const int blk = blockIdx.x;
    const int tid = threadIdx.x;
    const int wid = tid >> 5, lid = tid & 31;

    if (blk < GBLK) {
        // ===== g block e: warp w streams o-rows [16w,16w+16) as float4 =====
        const int e = blk;
        __shared__ float  s_w[Ec];
        __shared__ float4 sp4[8][32];            // per-warp k-quad partials

        if (tid < Ec) s_w[tid] = out_w[tid];
        __syncthreads();

        // row o of fc_w viewed as float4: quad index = o*4096 + e*32 + lane
        const float4* fw4 = (const float4*)fc_w + e * 32 + lid;
        const int o0 = wid * 16;
        float4 vals[16];
#pragma unroll
        for (int u = 0; u < 16; u++)
            vals[u] = fw4[(size_t)(o0 + u) * 4096];   // 16 LDG.128 in flight
        float ax = 0.f, ay = 0.f, az = 0.f, aw = 0.f;
#pragma unroll
        for (int u = 0; u < 16; u++) {
            const float wo = s_w[o0 + u];
            ax = fmaf(wo, vals[u].x, ax);
            ay = fmaf(wo, vals[u].y, ay);
            az = fmaf(wo, vals[u].z, az);
            aw = fmaf(wo, vals[u].w, aw);
        }
        sp4[wid][lid] = make_float4(ax, ay, az, aw);
        __syncthreads();

        if (tid < Wc) {                           // k = tid
            const float* spf = (const float*)sp4; // [8][128] floats
            float s = 0.0f;
#pragma unroll
            for (int w = 0; w < 8; w++)
                s += spf[w * 128 + tid];          // bank = k%32: conflict-free
            d_g[e * Wc + tid] = s;
        }
        __threadfence();
        __syncthreads();
        if (tid == 0) atomicAdd(&d_arrive, 1);
        return;
    }

    // ========== final block: batch b = blk - GBLK (self-contained) ==========
    const int b = blk - GBLK;
    const int k = tid & 127;             // window tap
    const int h = tid >> 7;              // e-half
    __shared__ int   sred[NT / 32];
    __shared__ float sfl[NT / 32];
    __shared__ int   s_tok[Wc];
    __shared__ float s_emb[8 * 129];     // row 7 zeroed (pad sentinel)

    for (int i = tid; i < 8 * Ec; i += NT)
        s_emb[(i >> 7) * 129 + (i & 127)] = (i < Vc * Ec) ? emb[i] : 0.0f;

    // dtype detection: tokens in [0,7) => int64 iff all odd 32-bit words of the
    // first 8KB are zero (8KB in-bounds for both layouts).
    const int* xw = (const int*)xraw;
    int any = 0;
    for (int i = tid; i < 2048; i += NT)
        if ((i & 1) && xw[i] != 0) any = 1;
    any = __any_sync(0xffffffffu, any) ? 1 : 0;
    if (lid == 0) sred[wid] = any;
    __syncthreads();
    int is32 = 0;
#pragma unroll
    for (int i = 0; i < NT / 32; i++) is32 |= sred[i];
    __syncthreads();

    // count non-pad tokens in row b
    int cnt = 0;
    if (is32) {
        const int* xr = (const int*)xraw + b * Sc;
#pragma unroll
        for (int s = tid; s < Sc; s += NT) cnt += (xr[s] != 0);
    } else {
        const long long* xr = (const long long*)xraw + b * Sc;
#pragma unroll
        for (int s = tid; s < Sc; s += NT) cnt += (xr[s] != 0);
    }
#pragma unroll
    for (int off = 16; off; off >>= 1)
        cnt += __shfl_down_sync(0xffffffffu, cnt, off);
    if (lid == 0) sred[wid] = cnt;
    __syncthreads();
    int t = -1;
#pragma unroll
    for (int i = 0; i < NT / 32; i++) t += sred[i];

    // window tokens -> shared (sentinel 7 = pad -> zero emb row)
    if (tid < Wc) {
        const int p = t - (Wc - 1) + tid;
        int tok = Vc;
        if (p >= 0)
            tok = is32 ? ((const int*)xraw)[b * Sc + p]
                       : (int)((const long long*)xraw)[b * Sc + p];
        s_tok[tid] = tok;
    }
    __syncthreads();

    // wait for all g rows
    if (tid == 0)
        while (*(volatile int*)&d_arrive < GBLK) __nanosleep(32);
    __syncthreads();
    __threadfence();   // acquire d_g

    // thread (k,h): tap k, e in [64h, 64h+64); 2 staged batches of 32 L2 loads
    const int tok = s_tok[k];
    float acc = (h == 0) ? out_w[k] * fc_b[k] : 0.0f;   // fold bias dot
    const float* er = &s_emb[tok * 129 + h * 64];
    const float* gp = &d_g[(h * 64) * Wc + k];
#pragma unroll
    for (int bb = 0; bb < 2; bb++) {
        float vals[32];
#pragma unroll
        for (int u = 0; u < 32; u++)
            vals[u] = gp[(bb * 32 + u) * Wc];
#pragma unroll
        for (int u = 0; u < 32; u++)
            acc = fmaf(er[bb * 32 + u], vals[u], acc);
    }

#pragma unroll
    for (int off = 16; off; off >>= 1)
        acc += __shfl_down_sync(0xffffffffu, acc, off);
    if (lid == 0) sfl[wid] = acc;
    __syncthreads();
    if (tid == 0) {
        float s = 0.0f;
#pragma unroll
        for (int i = 0; i < NT / 32; i++) s += sfl[i];
        out[b] = s + out_b[0];
    }

    // reset counters for next graph replay
    __threadfence();
    __syncthreads();
    if (tid == 0) {
        int d = atomicAdd(&d_done, 1);
        if (d == Bc - 1) {      // last final block; every spin already released
            d_arrive = 0;
            d_done   = 0;
            __threadfence();
        }
    }
}

extern "C" void kernel_launch(void* const* d_in, const int* in_sizes, int n_in,
                              void* d_out, int out_size) {
    const void*  x     = d_in[0];                      // [16,2048] int64 or int32
    const float* emb   = (const float*)d_in[1];        // [7,128]
    const float* fc_w  = (const float*)d_in[2];        // [128,16384]
    const float* fc_b  = (const float*)d_in[3];        // [128]
    const float* out_w = (const float*)d_in[4];        // [1,128]
    const float* out_b = (const float*)d_in[5];        // [1]
    float* out = (float*)d_out;                        // [16]

    fused_kernel<<<GBLK + Bc, NT>>>(x, emb, fc_w, fc_b, out_w, out_b, out);
}